// round 10
// baseline (speedup 1.0000x reference)
#include <cuda_runtime.h>
#include <cuda_fp16.h>
#include <cstdint>

// PQLinear: out[32,11008] = x[32,4096] @ W + bias,
//   W[k, d*8+j] = vectors[d, indexes[k,d], j]
// Fused dequant (fp16) + mma.sync.m16n8k16, fp32 accum, split-K=2.

#define IN_DIM  4096
#define OUT_DIM 11008
#define NS      1376
#define KS      256
#define DS      8
#define BATCH   32

#define NSUB    4                  // subspaces per CTA (N=32)
#define K_TILE  64
#define SPLIT   2
#define K_STEPS (IN_DIM / K_TILE / SPLIT)  // 32 per CTA
#define NTHR    256
#define NBLK    (NS / NSUB)        // 344

#define A_PAD 72   // halfs/row (144B): 8-row ldmatrix conflict-free
#define B_PAD 40   // halfs/row (80B):  8-row ldmatrix conflict-free

__device__ __align__(16) __half g_vh[NS * KS * DS];
__device__ __align__(16) __half g_xh[BATCH * IN_DIM];
__device__ float g_part[SPLIT][BATCH][OUT_DIM];

__global__ void convert_kernel(const float* __restrict__ v,
                               const float* __restrict__ x) {
    int i = blockIdx.x * blockDim.x + threadIdx.x;
    if (i < NS * KS * DS) g_vh[i] = __float2half_rn(v[i]);
    if (i < BATCH * IN_DIM) g_xh[i] = __float2half_rn(x[i]);
}

__global__ void reduce_kernel(const float* __restrict__ bias,
                              float* __restrict__ out) {
    int i = blockIdx.x * blockDim.x + threadIdx.x;
    if (i < BATCH * OUT_DIM) {
        int n = i % OUT_DIM;
        out[i] = g_part[0][0][i] + g_part[1][0][i] + bias[n];
    }
}

__device__ __forceinline__ void cp16(uint32_t dst, const void* src) {
    asm volatile("cp.async.cg.shared.global [%0], [%1], 16;\n"
                 :: "r"(dst), "l"(src));
}
__device__ __forceinline__ void ldmatrix_x4(uint32_t& a0, uint32_t& a1,
                                            uint32_t& a2, uint32_t& a3,
                                            uint32_t addr) {
    asm volatile("ldmatrix.sync.aligned.m8n8.x4.shared.b16 {%0,%1,%2,%3}, [%4];"
                 : "=r"(a0), "=r"(a1), "=r"(a2), "=r"(a3) : "r"(addr));
}
__device__ __forceinline__ void ldmatrix_x2t(uint32_t& b0, uint32_t& b1,
                                             uint32_t addr) {
    asm volatile("ldmatrix.sync.aligned.m8n8.x2.trans.shared.b16 {%0,%1}, [%2];"
                 : "=r"(b0), "=r"(b1) : "r"(addr));
}
__device__ __forceinline__ void mma16816(float& d0, float& d1, float& d2,
                                         float& d3, uint32_t a0, uint32_t a1,
                                         uint32_t a2, uint32_t a3,
                                         uint32_t b0, uint32_t b1) {
    asm volatile(
        "mma.sync.aligned.m16n8k16.row.col.f32.f16.f16.f32 "
        "{%0,%1,%2,%3}, {%4,%5,%6,%7}, {%8,%9}, {%0,%1,%2,%3};"
        : "+f"(d0), "+f"(d1), "+f"(d2), "+f"(d3)
        : "r"(a0), "r"(a1), "r"(a2), "r"(a3), "r"(b0), "r"(b1));
}

struct Smem {
    __align__(16) __half cb[NSUB * KS * DS];        // 16 KB codebooks
    __align__(16) __half A[2][BATCH * A_PAD];       // 2 x 4.5 KB
    __align__(16) __half B[2][K_TILE * B_PAD];      // 2 x 5 KB
    __align__(16) int    I[2][K_TILE * NSUB];       // 2 x 1 KB
};

__device__ __forceinline__ void load_step(Smem* sm, int s, int buf, int t,
                                          int d0, const int* __restrict__ idxg) {
    // A: 32 rows x 128B (64 fp16) -> padded rows. 256 x 16B, 1 op/thread.
    {
        int row = t >> 3, ch = t & 7;
        uint32_t dst = (uint32_t)__cvta_generic_to_shared(
            &sm->A[buf][row * A_PAD + ch * 8]);
        cp16(dst, g_xh + (size_t)row * IN_DIM + s * K_TILE + ch * 8);
    }
    // idx: 64 k-rows x 4 ints (16B, aligned: d0%4==0, row stride 5504B).
    if (t < K_TILE) {
        uint32_t dst = (uint32_t)__cvta_generic_to_shared(&sm->I[buf][t * 4]);
        cp16(dst, idxg + (size_t)(s * K_TILE + t) * NS + d0);
    }
}

__global__ __launch_bounds__(NTHR)
void pq_mma_kernel(const int* __restrict__ idxg) {
    __shared__ Smem sm;
    const int t = threadIdx.x;
    const int w = t >> 5, lane = t & 31;
    const int sub = w & 3;          // subspace within CTA
    const int mt  = w >> 2;         // m-tile (0: rows 0-15, 1: rows 16-31)
    const int d0 = blockIdx.x * NSUB;
    const int n0 = d0 * DS;
    const int split = blockIdx.y;
    const int s0 = split * K_STEPS; // global step offset

    // Prologue: codebooks (1024 x 16B, 4 ops/thread) + tiles for step 0.
    {
        const __half* src = g_vh + (size_t)d0 * KS * DS;
        #pragma unroll
        for (int r = 0; r < 4; r++) {
            int c = t + r * NTHR;
            uint32_t dst = (uint32_t)__cvta_generic_to_shared(&sm.cb[c * 8]);
            cp16(dst, src + c * 8);
        }
        load_step(&sm, s0, 0, t, d0, idxg);
        asm volatile("cp.async.commit_group;\n");
    }

    float d[4] = {};
    const float4* cb4 = (const float4*)sm.cb;

    for (int s = 0; s < K_STEPS; s++) {
        const int cur = s & 1;
        // (1) all warps done reading buf cur^1 before overwriting it
        __syncthreads();
        if (s + 1 < K_STEPS) {
            load_step(&sm, s0 + s + 1, cur ^ 1, t, d0, idxg);
            asm volatile("cp.async.commit_group;\n");
            asm volatile("cp.async.wait_group 1;\n");
        } else {
            asm volatile("cp.async.wait_group 0;\n");
        }
        // (2) make all threads' group-s data globally visible
        __syncthreads();

        // Dequant: 256 codewords, 1/thread. cw = k*4 + dl.
        {
            int k = t >> 2, dl = t & 3;
            int kidx = sm.I[cur][k * 4 + dl];
            float4 v = cb4[dl * KS + kidx];
            *(float4*)&sm.B[cur][k * B_PAD + dl * DS] = v;
        }
        // (3) B tile visible before ldmatrix
        __syncthreads();

        // MMA: warp (mt, sub): one m16n8 tile over k=64.
        uint32_t aB = (uint32_t)__cvta_generic_to_shared(&sm.A[cur][0]);
        uint32_t bB = (uint32_t)__cvta_generic_to_shared(&sm.B[cur][0]);
        #pragma unroll
        for (int kk = 0; kk < 4; kk++) {
            uint32_t b0, b1;
            ldmatrix_x2t(b0, b1,
                bB + ((kk * 16 + (lane & 15)) * B_PAD + sub * DS) * 2);
            uint32_t a0, a1, a2, a3;
            ldmatrix_x4(a0, a1, a2, a3,
                aB + (mt * 16 + (lane & 15)) * A_PAD * 2 +
                kk * 32 + (lane >> 4) * 16);
            mma16816(d[0], d[1], d[2], d[3], a0, a1, a2, a3, b0, b1);
        }
    }

    // Epilogue: m16n8 frag -> g_part[split] (no bias; reduce adds it).
    const int cr = lane >> 2, cc = (lane & 3) * 2;
    const int n = n0 + sub * DS + cc;
    const int row = mt * 16 + cr;
    float* p = &g_part[split][0][0];
    p[(size_t)row * OUT_DIM + n]           = d[0];
    p[(size_t)row * OUT_DIM + n + 1]       = d[1];
    p[(size_t)(row + 8) * OUT_DIM + n]     = d[2];
    p[(size_t)(row + 8) * OUT_DIM + n + 1] = d[3];
}

extern "C" void kernel_launch(void* const* d_in, const int* in_sizes, int n_in,
                              void* d_out, int out_size) {
    const float* x       = (const float*)d_in[0];
    const float* vectors = (const float*)d_in[1];
    const float* bias    = (const float*)d_in[2];
    const int*   indexes = (const int*)d_in[3];
    float*       out     = (float*)d_out;

    convert_kernel<<<(NS * KS * DS + 255) / 256, 256>>>(vectors, x);
    dim3 grid(NBLK, SPLIT);
    pq_mma_kernel<<<grid, NTHR>>>(indexes);
    reduce_kernel<<<(BATCH * OUT_DIM + 255) / 256, 256>>>(bias, out);
}

// round 11
// speedup vs baseline: 1.1740x; 1.1740x over previous
#include <cuda_runtime.h>
#include <cuda_fp16.h>
#include <cstdint>

// PQLinear: out[32,11008] = x[32,4096] @ W + bias,
//   W[k, d*8+j] = vectors[d, indexes[k,d], j]
// Fused dequant (fp16) + mma.sync.m16n8k16, fp32 accum, split-K=2.
// Warp map: (mt, sub-pair, kk-half); kk-half partials reduced via smem.

#define IN_DIM  4096
#define OUT_DIM 11008
#define NS      1376
#define KS      256
#define DS      8
#define BATCH   32

#define NSUB    4                  // subspaces per CTA (N=32)
#define K_TILE  64
#define SPLIT   2
#define K_STEPS (IN_DIM / K_TILE / SPLIT)  // 32 per CTA
#define NTHR    256
#define NBLK    (NS / NSUB)        // 344

#define A_PAD 72   // halfs/row (144B): 8-row ldmatrix conflict-free
#define B_PAD 40   // halfs/row (80B):  8-row ldmatrix conflict-free

#define NV4 (NS * KS * DS / 4)     // 704512
#define NX4 (BATCH * IN_DIM / 4)   // 32768

__device__ __align__(16) __half g_vh[NS * KS * DS];
__device__ __align__(16) __half g_xh[BATCH * IN_DIM];
__device__ float g_part[SPLIT][BATCH][OUT_DIM];

__global__ void convert_kernel(const float4* __restrict__ v,
                               const float4* __restrict__ x) {
    int i = blockIdx.x * blockDim.x + threadIdx.x;
    float4 f;
    __half2* dst;
    if (i < NV4) {
        f = v[i];
        dst = (__half2*)(g_vh + (size_t)i * 4);
    } else if (i < NV4 + NX4) {
        int j = i - NV4;
        f = x[j];
        dst = (__half2*)(g_xh + (size_t)j * 4);
    } else {
        return;
    }
    dst[0] = __floats2half2_rn(f.x, f.y);
    dst[1] = __floats2half2_rn(f.z, f.w);
}

__global__ void reduce_kernel(const float4* __restrict__ bias4,
                              float4* __restrict__ out4) {
    int i = blockIdx.x * blockDim.x + threadIdx.x;
    if (i < BATCH * OUT_DIM / 4) {
        const float4* p0 = (const float4*)&g_part[0][0][0];
        const float4* p1 = (const float4*)&g_part[1][0][0];
        float4 a = p0[i], b = p1[i], c = bias4[i % (OUT_DIM / 4)];
        float4 r;
        r.x = a.x + b.x + c.x;
        r.y = a.y + b.y + c.y;
        r.z = a.z + b.z + c.z;
        r.w = a.w + b.w + c.w;
        out4[i] = r;
    }
}

__device__ __forceinline__ void cp16(uint32_t dst, const void* src) {
    asm volatile("cp.async.cg.shared.global [%0], [%1], 16;\n"
                 :: "r"(dst), "l"(src));
}
__device__ __forceinline__ void ldmatrix_x4(uint32_t& a0, uint32_t& a1,
                                            uint32_t& a2, uint32_t& a3,
                                            uint32_t addr) {
    asm volatile("ldmatrix.sync.aligned.m8n8.x4.shared.b16 {%0,%1,%2,%3}, [%4];"
                 : "=r"(a0), "=r"(a1), "=r"(a2), "=r"(a3) : "r"(addr));
}
__device__ __forceinline__ void ldmatrix_x2t(uint32_t& b0, uint32_t& b1,
                                             uint32_t addr) {
    asm volatile("ldmatrix.sync.aligned.m8n8.x2.trans.shared.b16 {%0,%1}, [%2];"
                 : "=r"(b0), "=r"(b1) : "r"(addr));
}
__device__ __forceinline__ void mma16816(float& d0, float& d1, float& d2,
                                         float& d3, uint32_t a0, uint32_t a1,
                                         uint32_t a2, uint32_t a3,
                                         uint32_t b0, uint32_t b1) {
    asm volatile(
        "mma.sync.aligned.m16n8k16.row.col.f32.f16.f16.f32 "
        "{%0,%1,%2,%3}, {%4,%5,%6,%7}, {%8,%9}, {%0,%1,%2,%3};"
        : "+f"(d0), "+f"(d1), "+f"(d2), "+f"(d3)
        : "r"(a0), "r"(a1), "r"(a2), "r"(a3), "r"(b0), "r"(b1));
}

struct Smem {
    __align__(16) __half cb[NSUB * KS * DS];        // 16 KB codebooks
    __align__(16) __half A[2][BATCH * A_PAD];       // 2 x 4.5 KB
    __align__(16) __half B[2][K_TILE * B_PAD];      // 2 x 5 KB
    __align__(16) int    I[2][K_TILE * NSUB];       // 2 x 1 KB
};

__device__ __forceinline__ void load_step(Smem* sm, int s, int buf, int t,
                                          int d0, const int* __restrict__ idxg) {
    // A: 32 rows x 128B (64 fp16) -> padded rows. 256 x 16B, 1 op/thread.
    {
        int row = t >> 3, ch = t & 7;
        uint32_t dst = (uint32_t)__cvta_generic_to_shared(
            &sm->A[buf][row * A_PAD + ch * 8]);
        cp16(dst, g_xh + (size_t)row * IN_DIM + s * K_TILE + ch * 8);
    }
    // idx: 64 k-rows x 4 ints (16B, aligned: d0%4==0, row stride 5504B).
    if (t < K_TILE) {
        uint32_t dst = (uint32_t)__cvta_generic_to_shared(&sm->I[buf][t * 4]);
        cp16(dst, idxg + (size_t)(s * K_TILE + t) * NS + d0);
    }
}

__global__ __launch_bounds__(NTHR, 4)
void pq_mma_kernel(const int* __restrict__ idxg) {
    __shared__ Smem sm;
    const int t = threadIdx.x;
    const int w = t >> 5, lane = t & 31;
    const int mt = w & 1;           // m-tile (rows mt*16 .. mt*16+15)
    const int sp = (w >> 1) & 1;    // sub-pair (cols sp*16 .. sp*16+15)
    const int kh = w >> 2;          // kk half (kk in {2kh, 2kh+1})
    const int d0 = blockIdx.x * NSUB;
    const int n0 = d0 * DS;
    const int split = blockIdx.y;
    const int s0 = split * K_STEPS;

    // Prologue: codebooks (1024 x 16B, 4 ops/thread) + tiles for step 0.
    {
        const __half* src = g_vh + (size_t)d0 * KS * DS;
        #pragma unroll
        for (int r = 0; r < 4; r++) {
            int c = t + r * NTHR;
            uint32_t dst = (uint32_t)__cvta_generic_to_shared(&sm.cb[c * 8]);
            cp16(dst, src + c * 8);
        }
        load_step(&sm, s0, 0, t, d0, idxg);
        asm volatile("cp.async.commit_group;\n");
    }

    float d[2][4] = {};
    const float4* cb4 = (const float4*)sm.cb;

    for (int s = 0; s < K_STEPS; s++) {
        const int cur = s & 1;
        // (1) all warps done reading buf cur^1 before overwriting it
        __syncthreads();
        if (s + 1 < K_STEPS) {
            load_step(&sm, s0 + s + 1, cur ^ 1, t, d0, idxg);
            asm volatile("cp.async.commit_group;\n");
            asm volatile("cp.async.wait_group 1;\n");
        } else {
            asm volatile("cp.async.wait_group 0;\n");
        }
        // (2) make all threads' group-s data globally visible
        __syncthreads();

        // Dequant: 256 codewords, 1/thread. cw = k*4 + dl.
        {
            int k = t >> 2, dl = t & 3;
            int kidx = sm.I[cur][k * 4 + dl];
            float4 v = cb4[dl * KS + kidx];
            *(float4*)&sm.B[cur][k * B_PAD + dl * DS] = v;
        }
        // Hoisted A fragment loads (A[cur] valid since barrier (2));
        // overlaps the dequant STS, shortens post-(3) critical path.
        uint32_t aB = (uint32_t)__cvta_generic_to_shared(&sm.A[cur][0]);
        uint32_t a[2][4];
        #pragma unroll
        for (int kkl = 0; kkl < 2; kkl++) {
            int kk = kh * 2 + kkl;
            ldmatrix_x4(a[kkl][0], a[kkl][1], a[kkl][2], a[kkl][3],
                aB + (mt * 16 + (lane & 15)) * A_PAD * 2 +
                kk * 32 + (lane >> 4) * 16);
        }
        // (3) B tile visible before ldmatrix
        __syncthreads();

        uint32_t bB = (uint32_t)__cvta_generic_to_shared(&sm.B[cur][0]);
        #pragma unroll
        for (int kkl = 0; kkl < 2; kkl++) {
            int kk = kh * 2 + kkl;
            #pragma unroll
            for (int nn = 0; nn < 2; nn++) {
                uint32_t b0, b1;
                ldmatrix_x2t(b0, b1,
                    bB + ((kk * 16 + (lane & 15)) * B_PAD +
                          (sp * 2 + nn) * DS) * 2);
                mma16816(d[nn][0], d[nn][1], d[nn][2], d[nn][3],
                         a[kkl][0], a[kkl][1], a[kkl][2], a[kkl][3], b0, b1);
            }
        }
    }

    // kk-half reduction: warps (mt,sp,kh=1) hand partials to (mt,sp,kh=0).
    __syncthreads();
    float* red = (float*)&sm.A[0][0];   // 4*32*9*4 = 4608 B == sizeof(A[0])
    const int widx = w & 3;             // (mt,sp) id
    if (kh == 1) {
        float* p = red + (widx * 32 + lane) * 9;  // 9-stride: conflict-free
        #pragma unroll
        for (int nn = 0; nn < 2; nn++)
            #pragma unroll
            for (int q = 0; q < 4; q++)
                p[nn * 4 + q] = d[nn][q];
    }
    __syncthreads();
    if (kh == 0) {
        const float* p = red + (widx * 32 + lane) * 9;
        #pragma unroll
        for (int nn = 0; nn < 2; nn++)
            #pragma unroll
            for (int q = 0; q < 4; q++)
                d[nn][q] += p[nn * 4 + q];

        const int cr = lane >> 2, cc = (lane & 3) * 2;
        float* gp = &g_part[split][0][0];
        #pragma unroll
        for (int nn = 0; nn < 2; nn++) {
            const int n = n0 + sp * 16 + nn * 8 + cc;
            const int row = mt * 16 + cr;
            gp[(size_t)row * OUT_DIM + n]           = d[nn][0];
            gp[(size_t)row * OUT_DIM + n + 1]       = d[nn][1];
            gp[(size_t)(row + 8) * OUT_DIM + n]     = d[nn][2];
            gp[(size_t)(row + 8) * OUT_DIM + n + 1] = d[nn][3];
        }
    }
}

extern "C" void kernel_launch(void* const* d_in, const int* in_sizes, int n_in,
                              void* d_out, int out_size) {
    const float* x       = (const float*)d_in[0];
    const float* vectors = (const float*)d_in[1];
    const float* bias    = (const float*)d_in[2];
    const int*   indexes = (const int*)d_in[3];
    float*       out     = (float*)d_out;

    convert_kernel<<<(NV4 + NX4 + 255) / 256, 256>>>(
        (const float4*)vectors, (const float4*)x);
    dim3 grid(NBLK, SPLIT);
    pq_mma_kernel<<<grid, NTHR>>>(indexes);
    reduce_kernel<<<(BATCH * OUT_DIM / 4 + 255) / 256, 256>>>(
        (const float4*)bias, (float4*)out);
}

// round 12
// speedup vs baseline: 1.1806x; 1.0056x over previous
#include <cuda_runtime.h>
#include <cuda_fp16.h>
#include <cstdint>

// PQLinear: out[32,11008] = x[32,4096] @ W + bias,
//   W[k, d*8+j] = vectors[d, indexes[k,d], j]
// Fused dequant (fp16) + mma.sync.m16n8k16, fp32 accum, split-K=2.
// Codebooks converted fp32->fp16 in-kernel (prologue, overlapped).

#define IN_DIM  4096
#define OUT_DIM 11008
#define NS      1376
#define KS      256
#define DS      8
#define BATCH   32

#define NSUB    4                  // subspaces per CTA (N=32)
#define K_TILE  64
#define SPLIT   2
#define K_STEPS (IN_DIM / K_TILE / SPLIT)  // 32 per CTA
#define NTHR    256
#define NBLK    (NS / NSUB)        // 344

#define A_PAD 72   // halfs/row (144B): 8-row ldmatrix conflict-free
#define B_PAD 40   // halfs/row (80B):  8-row ldmatrix conflict-free

#define NX4 (BATCH * IN_DIM / 4)   // 32768

__device__ __align__(16) __half g_xh[BATCH * IN_DIM];
__device__ float g_part[SPLIT][BATCH][OUT_DIM];

__global__ void convert_x_kernel(const float4* __restrict__ x) {
    int i = blockIdx.x * blockDim.x + threadIdx.x;
    if (i < NX4) {
        float4 f = x[i];
        __half2* dst = (__half2*)(g_xh + (size_t)i * 4);
        dst[0] = __floats2half2_rn(f.x, f.y);
        dst[1] = __floats2half2_rn(f.z, f.w);
    }
}

__global__ void reduce_kernel(const float4* __restrict__ bias4,
                              float4* __restrict__ out4) {
    int i = blockIdx.x * blockDim.x + threadIdx.x;
    if (i < BATCH * OUT_DIM / 4) {
        const float4* p0 = (const float4*)&g_part[0][0][0];
        const float4* p1 = (const float4*)&g_part[1][0][0];
        float4 a = p0[i], b = p1[i], c = bias4[i % (OUT_DIM / 4)];
        float4 r;
        r.x = a.x + b.x + c.x;
        r.y = a.y + b.y + c.y;
        r.z = a.z + b.z + c.z;
        r.w = a.w + b.w + c.w;
        out4[i] = r;
    }
}

__device__ __forceinline__ void cp16(uint32_t dst, const void* src) {
    asm volatile("cp.async.cg.shared.global [%0], [%1], 16;\n"
                 :: "r"(dst), "l"(src));
}
__device__ __forceinline__ void ldmatrix_x4(uint32_t& a0, uint32_t& a1,
                                            uint32_t& a2, uint32_t& a3,
                                            uint32_t addr) {
    asm volatile("ldmatrix.sync.aligned.m8n8.x4.shared.b16 {%0,%1,%2,%3}, [%4];"
                 : "=r"(a0), "=r"(a1), "=r"(a2), "=r"(a3) : "r"(addr));
}
__device__ __forceinline__ void ldmatrix_x2t(uint32_t& b0, uint32_t& b1,
                                             uint32_t addr) {
    asm volatile("ldmatrix.sync.aligned.m8n8.x2.trans.shared.b16 {%0,%1}, [%2];"
                 : "=r"(b0), "=r"(b1) : "r"(addr));
}
__device__ __forceinline__ void mma16816(float& d0, float& d1, float& d2,
                                         float& d3, uint32_t a0, uint32_t a1,
                                         uint32_t a2, uint32_t a3,
                                         uint32_t b0, uint32_t b1) {
    asm volatile(
        "mma.sync.aligned.m16n8k16.row.col.f32.f16.f16.f32 "
        "{%0,%1,%2,%3}, {%4,%5,%6,%7}, {%8,%9}, {%0,%1,%2,%3};"
        : "+f"(d0), "+f"(d1), "+f"(d2), "+f"(d3)
        : "r"(a0), "r"(a1), "r"(a2), "r"(a3), "r"(b0), "r"(b1));
}

struct Smem {
    __align__(16) __half cb[NSUB * KS * DS];        // 16 KB codebooks (fp16)
    __align__(16) __half A[2][BATCH * A_PAD];       // 2 x 4.5 KB
    __align__(16) __half B[2][K_TILE * B_PAD];      // 2 x 5 KB
    __align__(16) int    I[2][K_TILE * NSUB];       // 2 x 1 KB
};

__device__ __forceinline__ void load_step(Smem* sm, int s, int buf, int t,
                                          int d0, const int* __restrict__ idxg) {
    // A: 32 rows x 128B (64 fp16) -> padded rows. 256 x 16B, 1 op/thread.
    {
        int row = t >> 3, ch = t & 7;
        uint32_t dst = (uint32_t)__cvta_generic_to_shared(
            &sm->A[buf][row * A_PAD + ch * 8]);
        cp16(dst, g_xh + (size_t)row * IN_DIM + s * K_TILE + ch * 8);
    }
    // idx: 64 k-rows x 4 ints (16B, aligned: d0%4==0, row stride 5504B).
    if (t < K_TILE) {
        uint32_t dst = (uint32_t)__cvta_generic_to_shared(&sm->I[buf][t * 4]);
        cp16(dst, idxg + (size_t)(s * K_TILE + t) * NS + d0);
    }
}

__global__ __launch_bounds__(NTHR, 4)
void pq_mma_kernel(const int* __restrict__ idxg,
                   const float* __restrict__ vectors) {
    __shared__ Smem sm;
    const int t = threadIdx.x;
    const int w = t >> 5, lane = t & 31;
    const int mt = w & 1;           // m-tile (rows mt*16 .. mt*16+15)
    const int sp = (w >> 1) & 1;    // sub-pair (cols sp*16 .. sp*16+15)
    const int kh = w >> 2;          // kk half (kk in {2kh, 2kh+1})
    const int d0 = blockIdx.x * NSUB;
    const int n0 = d0 * DS;
    const int split = blockIdx.y;
    const int s0 = split * K_STEPS;

    // Prologue: issue step-0 cp.asyncs first, then convert this CTA's 4
    // codebooks fp32->fp16 (LDG from L2-hot vectors, overlaps cp.async).
    load_step(&sm, s0, 0, t, d0, idxg);
    asm volatile("cp.async.commit_group;\n");
    {
        const float4* vsrc = (const float4*)(vectors + (size_t)d0 * KS * DS);
        #pragma unroll
        for (int r = 0; r < 8; r++) {
            int c = t + r * NTHR;           // 0..2047 float4s
            float4 f = vsrc[c];
            __half2* h = (__half2*)&sm.cb[c * 4];
            h[0] = __floats2half2_rn(f.x, f.y);
            h[1] = __floats2half2_rn(f.z, f.w);
        }
    }

    float d[2][4] = {};
    const float4* cb4 = (const float4*)sm.cb;

    for (int s = 0; s < K_STEPS; s++) {
        const int cur = s & 1;
        // (1) all warps done reading buf cur^1 before overwriting it
        __syncthreads();
        if (s + 1 < K_STEPS) {
            load_step(&sm, s0 + s + 1, cur ^ 1, t, d0, idxg);
            asm volatile("cp.async.commit_group;\n");
            asm volatile("cp.async.wait_group 1;\n");
        } else {
            asm volatile("cp.async.wait_group 0;\n");
        }
        // (2) make all threads' group-s data (and prologue cb) visible
        __syncthreads();

        // Dequant: 256 codewords, 1/thread. cw = k*4 + dl.
        {
            int k = t >> 2, dl = t & 3;
            int kidx = sm.I[cur][k * 4 + dl];
            float4 v = cb4[dl * KS + kidx];
            *(float4*)&sm.B[cur][k * B_PAD + dl * DS] = v;
        }
        // Hoisted A fragment loads (A[cur] valid since barrier (2));
        // overlaps the dequant STS.
        uint32_t aB = (uint32_t)__cvta_generic_to_shared(&sm.A[cur][0]);
        uint32_t a[2][4];
        #pragma unroll
        for (int kkl = 0; kkl < 2; kkl++) {
            int kk = kh * 2 + kkl;
            ldmatrix_x4(a[kkl][0], a[kkl][1], a[kkl][2], a[kkl][3],
                aB + (mt * 16 + (lane & 15)) * A_PAD * 2 +
                kk * 32 + (lane >> 4) * 16);
        }
        // (3) B tile visible before ldmatrix
        __syncthreads();

        uint32_t bB = (uint32_t)__cvta_generic_to_shared(&sm.B[cur][0]);
        #pragma unroll
        for (int kkl = 0; kkl < 2; kkl++) {
            int kk = kh * 2 + kkl;
            #pragma unroll
            for (int nn = 0; nn < 2; nn++) {
                uint32_t b0, b1;
                ldmatrix_x2t(b0, b1,
                    bB + ((kk * 16 + (lane & 15)) * B_PAD +
                          (sp * 2 + nn) * DS) * 2);
                mma16816(d[nn][0], d[nn][1], d[nn][2], d[nn][3],
                         a[kkl][0], a[kkl][1], a[kkl][2], a[kkl][3], b0, b1);
            }
        }
    }

    // kk-half reduction: warps (mt,sp,kh=1) hand partials to (mt,sp,kh=0).
    __syncthreads();
    float* red = (float*)&sm.A[0][0];   // 4*32*9*4 = 4608 B == sizeof(A[0])
    const int widx = w & 3;             // (mt,sp) id
    if (kh == 1) {
        float* p = red + (widx * 32 + lane) * 9;  // 9-stride: conflict-free
        #pragma unroll
        for (int nn = 0; nn < 2; nn++)
            #pragma unroll
            for (int q = 0; q < 4; q++)
                p[nn * 4 + q] = d[nn][q];
    }
    __syncthreads();
    if (kh == 0) {
        const float* p = red + (widx * 32 + lane) * 9;
        #pragma unroll
        for (int nn = 0; nn < 2; nn++)
            #pragma unroll
            for (int q = 0; q < 4; q++)
                d[nn][q] += p[nn * 4 + q];

        const int cr = lane >> 2, cc = (lane & 3) * 2;
        float* gp = &g_part[split][0][0];
        #pragma unroll
        for (int nn = 0; nn < 2; nn++) {
            const int n = n0 + sp * 16 + nn * 8 + cc;
            const int row = mt * 16 + cr;
            gp[(size_t)row * OUT_DIM + n]           = d[nn][0];
            gp[(size_t)row * OUT_DIM + n + 1]       = d[nn][1];
            gp[(size_t)(row + 8) * OUT_DIM + n]     = d[nn][2];
            gp[(size_t)(row + 8) * OUT_DIM + n + 1] = d[nn][3];
        }
    }
}

extern "C" void kernel_launch(void* const* d_in, const int* in_sizes, int n_in,
                              void* d_out, int out_size) {
    const float* x       = (const float*)d_in[0];
    const float* vectors = (const float*)d_in[1];
    const float* bias    = (const float*)d_in[2];
    const int*   indexes = (const int*)d_in[3];
    float*       out     = (float*)d_out;

    convert_x_kernel<<<(NX4 + 255) / 256, 256>>>((const float4*)x);
    dim3 grid(NBLK, SPLIT);
    pq_mma_kernel<<<grid, NTHR>>>(indexes, vectors);
    reduce_kernel<<<(BATCH * OUT_DIM / 4 + 255) / 256, 256>>>(
        (const float4*)bias, (float4*)out);
}

// round 15
// speedup vs baseline: 1.2472x; 1.0564x over previous
#include <cuda_runtime.h>
#include <cuda_fp16.h>
#include <cstdint>

// PQLinear: out[32,11008] = x[32,4096] @ W + bias,
//   W[k, d*8+j] = vectors[d, indexes[k,d], j]
// Fused dequant (fp16) + mma.sync.m16n8k16, fp32 accum, split-K=2.
// Warp map: (sp, kq) — each warp one k-quarter, both m-tiles, its n-half.
// Codebooks converted fp32->fp16 in-kernel (prologue, overlapped).

#define IN_DIM  4096
#define OUT_DIM 11008
#define NS      1376
#define KS      256
#define DS      8
#define BATCH   32

#define NSUB    4                  // subspaces per CTA (N=32)
#define K_TILE  64
#define SPLIT   2
#define K_STEPS (IN_DIM / K_TILE / SPLIT)  // 32 per CTA
#define NTHR    256
#define NBLK    (NS / NSUB)        // 344

#define A_PAD 72   // halfs/row (144B): 8-row ldmatrix conflict-free
#define B_PAD 40   // halfs/row (80B):  8-row ldmatrix conflict-free

#define NX4 (BATCH * IN_DIM / 4)   // 32768

__device__ __align__(16) __half g_xh[BATCH * IN_DIM];
__device__ float g_part[SPLIT][BATCH][OUT_DIM];

__global__ void convert_x_kernel(const float4* __restrict__ x) {
    int i = blockIdx.x * blockDim.x + threadIdx.x;
    if (i < NX4) {
        float4 f = x[i];
        __half2* dst = (__half2*)(g_xh + (size_t)i * 4);
        dst[0] = __floats2half2_rn(f.x, f.y);
        dst[1] = __floats2half2_rn(f.z, f.w);
    }
}

__global__ void reduce_kernel(const float4* __restrict__ bias4,
                              float4* __restrict__ out4) {
    int i = blockIdx.x * blockDim.x + threadIdx.x;
    if (i < BATCH * OUT_DIM / 4) {
        const float4* p0 = (const float4*)&g_part[0][0][0];
        const float4* p1 = (const float4*)&g_part[1][0][0];
        float4 a = p0[i], b = p1[i], c = bias4[i % (OUT_DIM / 4)];
        float4 r;
        r.x = a.x + b.x + c.x;
        r.y = a.y + b.y + c.y;
        r.z = a.z + b.z + c.z;
        r.w = a.w + b.w + c.w;
        out4[i] = r;
    }
}

__device__ __forceinline__ void cp16(uint32_t dst, const void* src) {
    asm volatile("cp.async.cg.shared.global [%0], [%1], 16;\n"
                 :: "r"(dst), "l"(src));
}
__device__ __forceinline__ void ldmatrix_x4(uint32_t& a0, uint32_t& a1,
                                            uint32_t& a2, uint32_t& a3,
                                            uint32_t addr) {
    asm volatile("ldmatrix.sync.aligned.m8n8.x4.shared.b16 {%0,%1,%2,%3}, [%4];"
                 : "=r"(a0), "=r"(a1), "=r"(a2), "=r"(a3) : "r"(addr));
}
__device__ __forceinline__ void ldmatrix_x2t(uint32_t& b0, uint32_t& b1,
                                             uint32_t addr) {
    asm volatile("ldmatrix.sync.aligned.m8n8.x2.trans.shared.b16 {%0,%1}, [%2];"
                 : "=r"(b0), "=r"(b1) : "r"(addr));
}
__device__ __forceinline__ void mma16816(float& d0, float& d1, float& d2,
                                         float& d3, uint32_t a0, uint32_t a1,
                                         uint32_t a2, uint32_t a3,
                                         uint32_t b0, uint32_t b1) {
    asm volatile(
        "mma.sync.aligned.m16n8k16.row.col.f32.f16.f16.f32 "
        "{%0,%1,%2,%3}, {%4,%5,%6,%7}, {%8,%9}, {%0,%1,%2,%3};"
        : "+f"(d0), "+f"(d1), "+f"(d2), "+f"(d3)
        : "r"(a0), "r"(a1), "r"(a2), "r"(a3), "r"(b0), "r"(b1));
}

struct Smem {
    __align__(16) __half cb[NSUB * KS * DS];        // 16 KB codebooks (fp16)
    __align__(16) __half A[2][BATCH * A_PAD];       // 2 x 4.5 KB
    __align__(16) __half B[2][K_TILE * B_PAD];      // 2 x 5 KB
    __align__(16) int    I[2][K_TILE * NSUB];       // 2 x 1 KB
};

__device__ __forceinline__ void load_step(Smem* sm, int s, int buf, int t,
                                          int d0, const int* __restrict__ idxg) {
    // A: 32 rows x 128B (64 fp16) -> padded rows. 256 x 16B, 1 op/thread.
    {
        int row = t >> 3, ch = t & 7;
        uint32_t dst = (uint32_t)__cvta_generic_to_shared(
            &sm->A[buf][row * A_PAD + ch * 8]);
        cp16(dst, g_xh + (size_t)row * IN_DIM + s * K_TILE + ch * 8);
    }
    // idx: 64 k-rows x 4 ints (16B, aligned: d0%4==0, row stride 5504B).
    if (t < K_TILE) {
        uint32_t dst = (uint32_t)__cvta_generic_to_shared(&sm->I[buf][t * 4]);
        cp16(dst, idxg + (size_t)(s * K_TILE + t) * NS + d0);
    }
}

__global__ __launch_bounds__(NTHR, 4)
void pq_mma_kernel(const int* __restrict__ idxg,
                   const float* __restrict__ vectors) {
    __shared__ Smem sm;
    const int t = threadIdx.x;
    const int w = t >> 5, lane = t & 31;
    const int sp = w & 1;           // n-half (cols sp*16 .. sp*16+15)
    const int kq = w >> 1;          // k-quarter (kk = kq)
    const int d0 = blockIdx.x * NSUB;
    const int n0 = d0 * DS;
    const int split = blockIdx.y;
    const int s0 = split * K_STEPS;

    // Prologue: issue step-0 cp.asyncs first, then convert this CTA's 4
    // codebooks fp32->fp16 (LDG from L2-hot vectors, overlaps cp.async).
    load_step(&sm, s0, 0, t, d0, idxg);
    asm volatile("cp.async.commit_group;\n");
    {
        const float4* vsrc = (const float4*)(vectors + (size_t)d0 * KS * DS);
        #pragma unroll
        for (int r = 0; r < 8; r++) {
            int c = t + r * NTHR;           // 0..2047 float4s
            float4 f = vsrc[c];
            __half2* h = (__half2*)&sm.cb[c * 4];
            h[0] = __floats2half2_rn(f.x, f.y);
            h[1] = __floats2half2_rn(f.z, f.w);
        }
    }

    float d[2][2][4] = {};   // [mt][nn][frag]
    const float4* cb4 = (const float4*)sm.cb;

    for (int s = 0; s < K_STEPS; s++) {
        const int cur = s & 1;
        // (1) all warps done reading buf cur^1 before overwriting it
        __syncthreads();
        if (s + 1 < K_STEPS) {
            load_step(&sm, s0 + s + 1, cur ^ 1, t, d0, idxg);
            asm volatile("cp.async.commit_group;\n");
            asm volatile("cp.async.wait_group 1;\n");
        } else {
            asm volatile("cp.async.wait_group 0;\n");
        }
        // (2) make all threads' group-s data (and prologue cb) visible
        __syncthreads();

        // Dequant: 256 codewords, 1/thread. cw = k*4 + dl.
        {
            int k = t >> 2, dl = t & 3;
            int kidx = sm.I[cur][k * 4 + dl];
            float4 v = cb4[dl * KS + kidx];
            *(float4*)&sm.B[cur][k * B_PAD + dl * DS] = v;
        }
        // Hoisted A fragment loads (A[cur] valid since barrier (2));
        // overlaps the dequant STS. One k-quarter, both m-tiles.
        uint32_t aB = (uint32_t)__cvta_generic_to_shared(&sm.A[cur][0]);
        uint32_t a[2][4];
        #pragma unroll
        for (int mt = 0; mt < 2; mt++) {
            ldmatrix_x4(a[mt][0], a[mt][1], a[mt][2], a[mt][3],
                aB + (mt * 16 + (lane & 15)) * A_PAD * 2 +
                kq * 32 + (lane >> 4) * 16);
        }
        // (3) B tile visible before ldmatrix
        __syncthreads();

        uint32_t bB = (uint32_t)__cvta_generic_to_shared(&sm.B[cur][0]);
        #pragma unroll
        for (int nn = 0; nn < 2; nn++) {
            uint32_t b0, b1;
            ldmatrix_x2t(b0, b1,
                bB + ((kq * 16 + (lane & 15)) * B_PAD +
                      (sp * 2 + nn) * DS) * 2);
            #pragma unroll
            for (int mt = 0; mt < 2; mt++)
                mma16816(d[mt][nn][0], d[mt][nn][1], d[mt][nn][2], d[mt][nn][3],
                         a[mt][0], a[mt][1], a[mt][2], a[mt][3], b0, b1);
        }
    }

    // k-quarter reduction: warps kq=1..3 store partials; kq=0 accumulates.
    // Scratch overlays sm.A+sm.B (19456 B contiguous); need 6*32*17*4=13056 B.
    __syncthreads();
    float* red = (float*)&sm.A[0][0];
    if (kq >= 1) {
        float* p = red + ((sp * 3 + (kq - 1)) * 32 + lane) * 17;  // odd stride
        #pragma unroll
        for (int mt = 0; mt < 2; mt++)
            #pragma unroll
            for (int nn = 0; nn < 2; nn++)
                #pragma unroll
                for (int q = 0; q < 4; q++)
                    p[(mt * 2 + nn) * 4 + q] = d[mt][nn][q];
    }
    __syncthreads();
    if (kq == 0) {
        #pragma unroll
        for (int r = 0; r < 3; r++) {
            const float* p = red + ((sp * 3 + r) * 32 + lane) * 17;
            #pragma unroll
            for (int mt = 0; mt < 2; mt++)
                #pragma unroll
                for (int nn = 0; nn < 2; nn++)
                    #pragma unroll
                    for (int q = 0; q < 4; q++)
                        d[mt][nn][q] += p[(mt * 2 + nn) * 4 + q];
        }

        const int cr = lane >> 2, cc = (lane & 3) * 2;
        float* gp = &g_part[split][0][0];
        #pragma unroll
        for (int mt = 0; mt < 2; mt++) {
            #pragma unroll
            for (int nn = 0; nn < 2; nn++) {
                const int n = n0 + sp * 16 + nn * 8 + cc;
                const int row = mt * 16 + cr;
                gp[(size_t)row * OUT_DIM + n]           = d[mt][nn][0];
                gp[(size_t)row * OUT_DIM + n + 1]       = d[mt][nn][1];
                gp[(size_t)(row + 8) * OUT_DIM + n]     = d[mt][nn][2];
                gp[(size_t)(row + 8) * OUT_DIM + n + 1] = d[mt][nn][3];
            }
        }
    }
}

extern "C" void kernel_launch(void* const* d_in, const int* in_sizes, int n_in,
                              void* d_out, int out_size) {
    const float* x       = (const float*)d_in[0];
    const float* vectors = (const float*)d_in[1];
    const float* bias    = (const float*)d_in[2];
    const int*   indexes = (const int*)d_in[3];
    float*       out     = (float*)d_out;

    convert_x_kernel<<<(NX4 + 255) / 256, 256>>>((const float4*)x);
    dim3 grid(NBLK, SPLIT);
    pq_mma_kernel<<<grid, NTHR>>>(indexes, vectors);
    reduce_kernel<<<(BATCH * OUT_DIM / 4 + 255) / 256, 256>>>(
        (const float4*)bias, (float4*)out);
}

// round 16
// speedup vs baseline: 1.2963x; 1.0394x over previous
#include <cuda_runtime.h>
#include <cuda_fp16.h>
#include <cstdint>

// PQLinear: out[32,11008] = x[32,4096] @ W + bias,
//   W[k, d*8+j] = vectors[d, indexes[k,d], j]
// Fused dequant (fp16) + mma.sync.m16n8k16, fp32 accum, split-K=2.
// Warp map: (sp, kq). Pipelined: dequant(s+1) overlaps MMA(s); 2 barriers/step.

#define IN_DIM  4096
#define OUT_DIM 11008
#define NS      1376
#define KS      256
#define DS      8
#define BATCH   32

#define NSUB    4                  // subspaces per CTA (N=32)
#define K_TILE  64
#define SPLIT   2
#define K_STEPS (IN_DIM / K_TILE / SPLIT)  // 32 per CTA
#define NTHR    256
#define NBLK    (NS / NSUB)        // 344

#define A_PAD 72   // halfs/row (144B): 8-row ldmatrix conflict-free
#define B_PAD 40   // halfs/row (80B):  8-row ldmatrix conflict-free

#define NX4 (BATCH * IN_DIM / 4)   // 32768

__device__ __align__(16) __half g_xh[BATCH * IN_DIM];
__device__ float g_part[SPLIT][BATCH][OUT_DIM];

__global__ void convert_x_kernel(const float4* __restrict__ x) {
    int i = blockIdx.x * blockDim.x + threadIdx.x;
    if (i < NX4) {
        float4 f = x[i];
        __half2* dst = (__half2*)(g_xh + (size_t)i * 4);
        dst[0] = __floats2half2_rn(f.x, f.y);
        dst[1] = __floats2half2_rn(f.z, f.w);
    }
}

__global__ void reduce_kernel(const float4* __restrict__ bias4,
                              float4* __restrict__ out4) {
    int i = blockIdx.x * blockDim.x + threadIdx.x;
    if (i < BATCH * OUT_DIM / 4) {
        const float4* p0 = (const float4*)&g_part[0][0][0];
        const float4* p1 = (const float4*)&g_part[1][0][0];
        float4 a = p0[i], b = p1[i], c = bias4[i % (OUT_DIM / 4)];
        float4 r;
        r.x = a.x + b.x + c.x;
        r.y = a.y + b.y + c.y;
        r.z = a.z + b.z + c.z;
        r.w = a.w + b.w + c.w;
        out4[i] = r;
    }
}

__device__ __forceinline__ void cp16(uint32_t dst, const void* src) {
    asm volatile("cp.async.cg.shared.global [%0], [%1], 16;\n"
                 :: "r"(dst), "l"(src));
}
__device__ __forceinline__ void ldmatrix_x4(uint32_t& a0, uint32_t& a1,
                                            uint32_t& a2, uint32_t& a3,
                                            uint32_t addr) {
    asm volatile("ldmatrix.sync.aligned.m8n8.x4.shared.b16 {%0,%1,%2,%3}, [%4];"
                 : "=r"(a0), "=r"(a1), "=r"(a2), "=r"(a3) : "r"(addr));
}
__device__ __forceinline__ void ldmatrix_x2t(uint32_t& b0, uint32_t& b1,
                                             uint32_t addr) {
    asm volatile("ldmatrix.sync.aligned.m8n8.x2.trans.shared.b16 {%0,%1}, [%2];"
                 : "=r"(b0), "=r"(b1) : "r"(addr));
}
__device__ __forceinline__ void mma16816(float& d0, float& d1, float& d2,
                                         float& d3, uint32_t a0, uint32_t a1,
                                         uint32_t a2, uint32_t a3,
                                         uint32_t b0, uint32_t b1) {
    asm volatile(
        "mma.sync.aligned.m16n8k16.row.col.f32.f16.f16.f32 "
        "{%0,%1,%2,%3}, {%4,%5,%6,%7}, {%8,%9}, {%0,%1,%2,%3};"
        : "+f"(d0), "+f"(d1), "+f"(d2), "+f"(d3)
        : "r"(a0), "r"(a1), "r"(a2), "r"(a3), "r"(b0), "r"(b1));
}

struct Smem {
    __align__(16) __half cb[NSUB * KS * DS];        // 16 KB codebooks (fp16)
    __align__(16) __half A[2][BATCH * A_PAD];       // 2 x 4.5 KB
    __align__(16) __half B[2][K_TILE * B_PAD];      // 2 x 5 KB
    __align__(16) int    I[2][K_TILE * NSUB];       // 2 x 1 KB
};

__device__ __forceinline__ void load_step(Smem* sm, int s, int buf, int t,
                                          int d0, const int* __restrict__ idxg) {
    // A: 32 rows x 128B (64 fp16) -> padded rows. 256 x 16B, 1 op/thread.
    {
        int row = t >> 3, ch = t & 7;
        uint32_t dst = (uint32_t)__cvta_generic_to_shared(
            &sm->A[buf][row * A_PAD + ch * 8]);
        cp16(dst, g_xh + (size_t)row * IN_DIM + s * K_TILE + ch * 8);
    }
    // idx: 64 k-rows x 4 ints (16B, aligned: d0%4==0, row stride 5504B).
    if (t < K_TILE) {
        uint32_t dst = (uint32_t)__cvta_generic_to_shared(&sm->I[buf][t * 4]);
        cp16(dst, idxg + (size_t)(s * K_TILE + t) * NS + d0);
    }
}

__device__ __forceinline__ void dequant(Smem* sm, int buf, int t) {
    // 256 codewords, 1/thread. cw = k*4 + dl.
    const float4* cb4 = (const float4*)sm->cb;
    int k = t >> 2, dl = t & 3;
    int kidx = sm->I[buf][k * 4 + dl];
    float4 v = cb4[dl * KS + kidx];
    *(float4*)&sm->B[buf][k * B_PAD + dl * DS] = v;
}

__global__ __launch_bounds__(NTHR, 4)
void pq_mma_kernel(const int* __restrict__ idxg,
                   const float* __restrict__ vectors) {
    __shared__ Smem sm;
    const int t = threadIdx.x;
    const int w = t >> 5, lane = t & 31;
    const int sp = w & 1;           // n-half (cols sp*16 .. sp*16+15)
    const int kq = w >> 1;          // k-quarter (kk = kq)
    const int d0 = blockIdx.x * NSUB;
    const int n0 = d0 * DS;
    const int split = blockIdx.y;
    const int s0 = split * K_STEPS;

    // Prologue: prime 2 load groups, convert codebooks, dequant B[0].
    load_step(&sm, s0, 0, t, d0, idxg);
    asm volatile("cp.async.commit_group;\n");          // G(0)
    if (K_STEPS > 1) {
        load_step(&sm, s0 + 1, 1, t, d0, idxg);
        asm volatile("cp.async.commit_group;\n");      // G(1)
    }
    {
        const float4* vsrc = (const float4*)(vectors + (size_t)d0 * KS * DS);
        #pragma unroll
        for (int r = 0; r < 8; r++) {
            int c = t + r * NTHR;           // 0..2047 float4s
            float4 f = vsrc[c];
            __half2* h = (__half2*)&sm.cb[c * 4];
            h[0] = __floats2half2_rn(f.x, f.y);
            h[1] = __floats2half2_rn(f.z, f.w);
        }
    }
    asm volatile("cp.async.wait_group 1;\n");          // G(0) landed
    __syncthreads();                                   // publish A/I[0] + cb
    dequant(&sm, 0, t);
    __syncthreads();                                   // publish B[0]

    float d[2][2][4] = {};   // [mt][nn][frag]

    // Invariant at iter s: A/I/B[cur] published; G(s+1) outstanding.
    for (int s = 0; s < K_STEPS; s++) {
        const int cur = s & 1, nxt = cur ^ 1;

        // 1. Fragments + MMA for step s (tensor work overlaps stages 2-4).
        uint32_t aB = (uint32_t)__cvta_generic_to_shared(&sm.A[cur][0]);
        uint32_t bB = (uint32_t)__cvta_generic_to_shared(&sm.B[cur][0]);
        uint32_t a[2][4];
        #pragma unroll
        for (int mt = 0; mt < 2; mt++)
            ldmatrix_x4(a[mt][0], a[mt][1], a[mt][2], a[mt][3],
                aB + (mt * 16 + (lane & 15)) * A_PAD * 2 +
                kq * 32 + (lane >> 4) * 16);
        #pragma unroll
        for (int nn = 0; nn < 2; nn++) {
            uint32_t b0, b1;
            ldmatrix_x2t(b0, b1,
                bB + ((kq * 16 + (lane & 15)) * B_PAD +
                      (sp * 2 + nn) * DS) * 2);
            #pragma unroll
            for (int mt = 0; mt < 2; mt++)
                mma16816(d[mt][nn][0], d[mt][nn][1], d[mt][nn][2], d[mt][nn][3],
                         a[mt][0], a[mt][1], a[mt][2], a[mt][3], b0, b1);
        }

        // 2. G(s+1) landed; publish it. Also: all frag reads of A/B[cur] done.
        asm volatile("cp.async.wait_group 0;\n");
        __syncthreads();

        // 3. Issue G(s+2) into buf cur; dequant B[nxt] (overlaps MMA(s)).
        if (s + 2 < K_STEPS) {
            load_step(&sm, s0 + s + 2, cur, t, d0, idxg);
            asm volatile("cp.async.commit_group;\n");
        }
        if (s + 1 < K_STEPS) dequant(&sm, nxt, t);

        // 4. Publish B[nxt] for next iteration.
        __syncthreads();
    }

    // k-quarter reduction: warps kq=1..3 store partials; kq=0 accumulates.
    // Scratch overlays sm.A+sm.B (19456 B contiguous); need 6*32*17*4=13056 B.
    float* red = (float*)&sm.A[0][0];
    if (kq >= 1) {
        float* p = red + ((sp * 3 + (kq - 1)) * 32 + lane) * 17;  // odd stride
        #pragma unroll
        for (int mt = 0; mt < 2; mt++)
            #pragma unroll
            for (int nn = 0; nn < 2; nn++)
                #pragma unroll
                for (int q = 0; q < 4; q++)
                    p[(mt * 2 + nn) * 4 + q] = d[mt][nn][q];
    }
    __syncthreads();
    if (kq == 0) {
        #pragma unroll
        for (int r = 0; r < 3; r++) {
            const float* p = red + ((sp * 3 + r) * 32 + lane) * 17;
            #pragma unroll
            for (int mt = 0; mt < 2; mt++)
                #pragma unroll
                for (int nn = 0; nn < 2; nn++)
                    #pragma unroll
                    for (int q = 0; q < 4; q++)
                        d[mt][nn][q] += p[(mt * 2 + nn) * 4 + q];
        }

        const int cr = lane >> 2, cc = (lane & 3) * 2;
        float* gp = &g_part[split][0][0];
        #pragma unroll
        for (int mt = 0; mt < 2; mt++) {
            #pragma unroll
            for (int nn = 0; nn < 2; nn++) {
                const int n = n0 + sp * 16 + nn * 8 + cc;
                const int row = mt * 16 + cr;
                gp[(size_t)row * OUT_DIM + n]           = d[mt][nn][0];
                gp[(size_t)row * OUT_DIM + n + 1]       = d[mt][nn][1];
                gp[(size_t)(row + 8) * OUT_DIM + n]     = d[mt][nn][2];
                gp[(size_t)(row + 8) * OUT_DIM + n + 1] = d[mt][nn][3];
            }
        }
    }
}

extern "C" void kernel_launch(void* const* d_in, const int* in_sizes, int n_in,
                              void* d_out, int out_size) {
    const float* x       = (const float*)d_in[0];
    const float* vectors = (const float*)d_in[1];
    const float* bias    = (const float*)d_in[2];
    const int*   indexes = (const int*)d_in[3];
    float*       out     = (float*)d_out;

    convert_x_kernel<<<(NX4 + 255) / 256, 256>>>((const float4*)x);
    dim3 grid(NBLK, SPLIT);
    pq_mma_kernel<<<grid, NTHR>>>(indexes, vectors);
    reduce_kernel<<<(BATCH * OUT_DIM / 4 + 255) / 256, 256>>>(
        (const float4*)bias, (float4*)out);
}